// round 9
// baseline (speedup 1.0000x reference)
#include <cuda_runtime.h>
#include <cuda_bf16.h>
#include <cstdint>

#define N_NODES 1024
#define E_EDGES 16384
#define IN_DIM  1300
#define H_HEADS 16
#define D_HEAD  512
#define F_DIM   8192
#define G_GRAPHS 8
#define ET (E_EDGES + N_NODES)
#define SLOPE 0.2f

#define KP1 1344              // IN_DIM padded to multiple of 32

// ---------------- scratch ----------------------------------------------------
__device__ float g_h[N_NODES * F_DIM];
__device__ float g_agg[N_NODES * F_DIM];
__device__ float g_ssrc[N_NODES * H_HEADS];
__device__ float g_sdst[N_NODES * H_HEADS];
__device__ int   g_src[ET];
__device__ int   g_dst[ET];
__device__ int   g_cnt[N_NODES];
__device__ int   g_off[N_NODES + 1];
__device__ int   g_cur[N_NODES];
__device__ int   g_csr_src[ET];
__device__ float g_alpha[ET * H_HEADS];
__device__ float g_nodeval[N_NODES];
// bf16 split buffers (reused by both layers)
__device__ __nv_bfloat16 g_Ah[N_NODES * F_DIM];
__device__ __nv_bfloat16 g_Al[N_NODES * F_DIM];
__device__ __nv_bfloat16 g_Bth[(size_t)F_DIM * F_DIM];
__device__ __nv_bfloat16 g_Btl[(size_t)F_DIM * F_DIM];

// ---------------- PTX helpers ------------------------------------------------
__device__ __forceinline__ uint32_t smem_u32(const void* p) {
    uint32_t a;
    asm("{ .reg .u64 t; cvta.to.shared.u64 t, %1; cvt.u32.u64 %0, t; }" : "=r"(a) : "l"(p));
    return a;
}
__device__ __forceinline__ void cp16(uint32_t dst, const void* src) {
    asm volatile("cp.async.cg.shared.global [%0], [%1], 16;\n" :: "r"(dst), "l"(src) : "memory");
}
__device__ __forceinline__ void cp_commit() {
    asm volatile("cp.async.commit_group;\n" ::: "memory");
}
__device__ __forceinline__ void cp_wait0() { asm volatile("cp.async.wait_group 0;\n" ::: "memory"); }
__device__ __forceinline__ void cp_wait2() { asm volatile("cp.async.wait_group 2;\n" ::: "memory"); }

__device__ __forceinline__ void mma_bf16(float* c, const uint32_t* a, uint32_t b0, uint32_t b1) {
    asm volatile(
        "mma.sync.aligned.m16n8k16.row.col.f32.bf16.bf16.f32 "
        "{%0,%1,%2,%3}, {%4,%5,%6,%7}, {%8,%9}, {%0,%1,%2,%3};\n"
        : "+f"(c[0]), "+f"(c[1]), "+f"(c[2]), "+f"(c[3])
        : "r"(a[0]), "r"(a[1]), "r"(a[2]), "r"(a[3]), "r"(b0), "r"(b1));
}

__device__ __forceinline__ void ldsm4(uint32_t* r, uint32_t addr) {
    asm volatile("ldmatrix.sync.aligned.m8n8.x4.shared.b16 {%0,%1,%2,%3}, [%4];"
                 : "=r"(r[0]), "=r"(r[1]), "=r"(r[2]), "=r"(r[3]) : "r"(addr));
}

// ---------------- conversion kernels -----------------------------------------
__global__ void convA_kernel(const float* __restrict__ A, int K, int Kp,
                             __nv_bfloat16* __restrict__ Ah, __nv_bfloat16* __restrict__ Al)
{
    int row = blockIdx.y;
    int col = blockIdx.x * 256 + threadIdx.x;
    if (col >= Kp) return;
    float v = (col < K) ? A[(size_t)row * K + col] : 0.f;
    __nv_bfloat16 h = __float2bfloat16(v);
    float r = v - __bfloat162float(h);
    size_t o = (size_t)row * Kp + col;
    Ah[o] = h;
    Al[o] = __float2bfloat16(r);
}

// B [K, F_DIM] fp32 -> Bt_hi/lo [F_DIM, Kp] bf16 (transposed, zero-padded in K)
__global__ void convBt_kernel(const float* __restrict__ B, int K, int Kp,
                              __nv_bfloat16* __restrict__ Bth, __nv_bfloat16* __restrict__ Btl)
{
    __shared__ float sm[32][33];
    int k0 = blockIdx.x * 32, n0 = blockIdx.y * 32;
    int tx = threadIdx.x, ty = threadIdx.y;
    int k = k0 + ty;
    sm[ty][tx] = (k < K) ? B[(size_t)k * F_DIM + n0 + tx] : 0.f;
    __syncthreads();
    float v = sm[tx][ty];
    __nv_bfloat16 h = __float2bfloat16(v);
    size_t o = (size_t)(n0 + ty) * Kp + k0 + tx;
    Bth[o] = h;
    Btl[o] = __float2bfloat16(v - __bfloat162float(h));
}

// ---------------- mma.sync GEMM: C[1024, 8192] = A[1024,Kp] @ Bt[8192,Kp]^T ---
// CTA tile 128x128, K-chunk 32, 3 pipeline stages.
// Stage layout (32KB): Ah[0,8K) Al[8K,16K) Bh[16K,24K) Bl[24K,32K)
#define STAGE_SZ 32768u
#define NSTAGE 3
#define GEMM_SMEM (STAGE_SZ * NSTAGE)

__global__ __launch_bounds__(256, 2) void mma_gemm_kernel(
    const __nv_bfloat16* __restrict__ Ah, const __nv_bfloat16* __restrict__ Al,
    const __nv_bfloat16* __restrict__ Bh, const __nv_bfloat16* __restrict__ Bl,
    float* __restrict__ C, int Kp, int nc)
{
    extern __shared__ __align__(128) char smem[];
    const uint32_t sb = smem_u32(smem);
    const int tid = threadIdx.x;
    const int wid = tid >> 5;
    const int lane = tid & 31;
    const int g = lane >> 2;       // 0..7
    const int t = lane & 3;        // 0..3
    const int wm = (wid >> 2) * 64;
    const int wn = (wid & 3) * 32;
    const int m0 = blockIdx.y * 128;
    const int n0 = blockIdx.x * 128;

    const __nv_bfloat16* aH = Ah + (size_t)m0 * Kp;
    const __nv_bfloat16* aL = Al + (size_t)m0 * Kp;
    const __nv_bfloat16* bH = Bh + (size_t)n0 * Kp;
    const __nv_bfloat16* bL = Bl + (size_t)n0 * Kp;

    float acc[4][4][4];
    #pragma unroll
    for (int i = 0; i < 4; i++)
        #pragma unroll
        for (int j = 0; j < 4; j++)
            #pragma unroll
            for (int q = 0; q < 4; q++) acc[i][j][q] = 0.f;

    // ldmatrix per-lane base offsets (within an 8KB [128 rows x 64B] region).
    // lane -> matrix index (lane>>3), row-in-matrix (lane&7).
    // A tile i at rows wm + i*16; k-half s flips bit5 (chunk^2 == +2 chunks).
    const int mtx = lane >> 3;
    const int mrow = lane & 7;
    const int arow = wm + (mtx & 1) * 8 + mrow;
    const uint32_t a_base = (uint32_t)(arow * 64 + ((((mtx >> 1)) ^ ((arow >> 1) & 3)) << 4));
    const int brow = wn + (mtx & 1) * 8 + mrow;
    const uint32_t b_base = (uint32_t)(brow * 64 + ((((mtx >> 1)) ^ ((brow >> 1) & 3)) << 4));

    // per-thread cp.async coords: 512 cp16 units per 8KB tile, 2 per thread
    const int r_u0 = tid >> 2,        ch_u0 = tid & 3;
    const int r_u1 = (tid + 256) >> 2, ch_u1 = (tid + 256) & 3;
    const uint32_t so0 = (uint32_t)(r_u0 * 64 + ((ch_u0 ^ ((r_u0 >> 1) & 3)) << 4));
    const uint32_t so1 = (uint32_t)(r_u1 * 64 + ((ch_u1 ^ ((r_u1 >> 1) & 3)) << 4));

    auto load_stage = [&](int c, int st) {
        const uint32_t base = sb + (uint32_t)st * STAGE_SZ;
        const int kc0 = c * 32;
        const size_t go0 = (size_t)r_u0 * Kp + kc0 + ch_u0 * 8;
        const size_t go1 = (size_t)r_u1 * Kp + kc0 + ch_u1 * 8;
        cp16(base + so0,          aH + go0);
        cp16(base + so1,          aH + go1);
        cp16(base + 8192 + so0,   aL + go0);
        cp16(base + 8192 + so1,   aL + go1);
        cp16(base + 16384 + so0,  bH + go0);
        cp16(base + 16384 + so1,  bH + go1);
        cp16(base + 24576 + so0,  bL + go0);
        cp16(base + 24576 + so1,  bL + go1);
        cp_commit();
    };

    load_stage(0, 0);
    if (nc > 1) load_stage(1, 1);

    for (int c = 0; c < nc; c++) {
        const int st = c % NSTAGE;
        if (c + 2 < nc) {
            load_stage(c + 2, (c + 2) % NSTAGE);
            cp_wait2();
        } else {
            cp_wait0();
        }
        __syncthreads();

        const uint32_t baseAh = sb + (uint32_t)st * STAGE_SZ;
        const uint32_t baseAl = baseAh + 8192;
        const uint32_t baseBh = baseAh + 16384;
        const uint32_t baseBl = baseAh + 24576;

        #pragma unroll
        for (int s = 0; s < 2; s++) {
            const uint32_t sx = (uint32_t)(s << 5);
            uint32_t ah[4][4], al[4][4], bh[4][2], bl[4][2];
            #pragma unroll
            for (int i = 0; i < 4; i++) {
                ldsm4(ah[i], baseAh + ((a_base + i * 1024u) ^ sx));
                ldsm4(al[i], baseAl + ((a_base + i * 1024u) ^ sx));
            }
            #pragma unroll
            for (int jp = 0; jp < 2; jp++) {
                uint32_t t4[4];
                ldsm4(t4, baseBh + ((b_base + jp * 1024u) ^ sx));
                bh[jp * 2][0] = t4[0]; bh[jp * 2 + 1][0] = t4[1];
                bh[jp * 2][1] = t4[2]; bh[jp * 2 + 1][1] = t4[3];
                ldsm4(t4, baseBl + ((b_base + jp * 1024u) ^ sx));
                bl[jp * 2][0] = t4[0]; bl[jp * 2 + 1][0] = t4[1];
                bl[jp * 2][1] = t4[2]; bl[jp * 2 + 1][1] = t4[3];
            }
            #pragma unroll
            for (int j = 0; j < 4; j++) {
                #pragma unroll
                for (int i = 0; i < 4; i++) {
                    mma_bf16(acc[i][j], ah[i], bh[j][0], bh[j][1]);
                    mma_bf16(acc[i][j], al[i], bh[j][0], bh[j][1]);
                    mma_bf16(acc[i][j], ah[i], bl[j][0], bl[j][1]);
                }
            }
        }
        __syncthreads();
    }

    // epilogue
    #pragma unroll
    for (int i = 0; i < 4; i++) {
        const int row0 = m0 + wm + i * 16 + g;
        #pragma unroll
        for (int j = 0; j < 4; j++) {
            const int col = n0 + wn + j * 8 + t * 2;
            float2* p0 = (float2*)(C + (size_t)row0 * F_DIM + col);
            float2* p1 = (float2*)(C + (size_t)(row0 + 8) * F_DIM + col);
            *p0 = make_float2(acc[i][j][0], acc[i][j][1]);
            *p1 = make_float2(acc[i][j][2], acc[i][j][3]);
        }
    }
}

// ---------------- attention scores ------------------------------------------
__global__ void scores_kernel(const float* __restrict__ h,
                              const float* __restrict__ asrc,
                              const float* __restrict__ adst)
{
    int n = blockIdx.x;
    int w = threadIdx.x >> 5;
    int lane = threadIdx.x & 31;
    const float* hp = h + (size_t)n * F_DIM + w * D_HEAD;
    const float* ap = asrc + w * D_HEAD;
    const float* bp = adst + w * D_HEAD;
    float s1 = 0.f, s2 = 0.f;
    #pragma unroll 4
    for (int d = lane; d < D_HEAD; d += 32) {
        float v = hp[d];
        s1 += v * ap[d];
        s2 += v * bp[d];
    }
    #pragma unroll
    for (int o = 16; o; o >>= 1) {
        s1 += __shfl_down_sync(0xffffffffu, s1, o);
        s2 += __shfl_down_sync(0xffffffffu, s2, o);
    }
    if (lane == 0) {
        g_ssrc[n * H_HEADS + w] = s1;
        g_sdst[n * H_HEADS + w] = s2;
    }
}

// ---------------- CSR build over dst -----------------------------------------
__global__ void zero_cnt_kernel() { g_cnt[threadIdx.x] = 0; }

__global__ void build_edges_kernel(const int* __restrict__ ei)
{
    int e = blockIdx.x * blockDim.x + threadIdx.x;
    if (e >= ET) return;
    int s, d;
    if (e < E_EDGES) { s = ei[e]; d = ei[E_EDGES + e]; }
    else             { s = e - E_EDGES; d = s; }
    g_src[e] = s;
    g_dst[e] = d;
    atomicAdd(&g_cnt[d], 1);
}

__global__ void scan_kernel()
{
    __shared__ int sm[N_NODES];
    int t = threadIdx.x;
    sm[t] = g_cnt[t];
    __syncthreads();
    for (int o = 1; o < N_NODES; o <<= 1) {
        int v = (t >= o) ? sm[t - o] : 0;
        __syncthreads();
        sm[t] += v;
        __syncthreads();
    }
    g_off[t + 1] = sm[t];
    int excl = (t == 0) ? 0 : sm[t - 1];
    if (t == 0) g_off[0] = 0;
    g_cur[t] = excl;
}

__global__ void scatter_kernel()
{
    int e = blockIdx.x * blockDim.x + threadIdx.x;
    if (e >= ET) return;
    int d = g_dst[e];
    int p = atomicAdd(&g_cur[d], 1);
    g_csr_src[p] = g_src[e];
}

// ---------------- segment softmax per (dst, head) ----------------------------
__global__ void attn_kernel()
{
    int n = blockIdx.x;
    int h = threadIdx.x >> 5;
    int lane = threadIdx.x & 31;
    int beg = g_off[n], end = g_off[n + 1];
    float sd = g_sdst[n * H_HEADS + h];

    float mx = -1e30f;
    for (int p = beg + lane; p < end; p += 32) {
        float e = g_ssrc[g_csr_src[p] * H_HEADS + h] + sd;
        e = (e > 0.f) ? e : SLOPE * e;
        mx = fmaxf(mx, e);
    }
    #pragma unroll
    for (int o = 16; o; o >>= 1)
        mx = fmaxf(mx, __shfl_xor_sync(0xffffffffu, mx, o));

    float sum = 0.f;
    for (int p = beg + lane; p < end; p += 32) {
        float e = g_ssrc[g_csr_src[p] * H_HEADS + h] + sd;
        e = (e > 0.f) ? e : SLOPE * e;
        float pv = __expf(e - mx);
        g_alpha[p * H_HEADS + h] = pv;
        sum += pv;
    }
    #pragma unroll
    for (int o = 16; o; o >>= 1)
        sum += __shfl_xor_sync(0xffffffffu, sum, o);

    float inv = 1.f / sum;
    for (int p = beg + lane; p < end; p += 32)
        g_alpha[p * H_HEADS + h] *= inv;
}

// ---------------- aggregation -------------------------------------------------
__global__ __launch_bounds__(256) void agg_kernel(
    const float* __restrict__ hin, const float* __restrict__ bias,
    float* __restrict__ out)
{
    int n = blockIdx.x;
    int tid = threadIdx.x;
    int hi = tid >> 7;
    int beg = g_off[n], end = g_off[n + 1];

    float4 acc[8];
    #pragma unroll
    for (int j = 0; j < 8; j++) acc[j] = make_float4(0.f, 0.f, 0.f, 0.f);

    for (int p = beg; p < end; p++) {
        int s = g_csr_src[p];
        const float4* hrow = (const float4*)(hin + (size_t)s * F_DIM);
        const float* al = &g_alpha[p * H_HEADS];
        #pragma unroll
        for (int j = 0; j < 8; j++) {
            float a = al[2 * j + hi];
            float4 v = hrow[j * 256 + tid];
            acc[j].x += a * v.x;
            acc[j].y += a * v.y;
            acc[j].z += a * v.z;
            acc[j].w += a * v.w;
        }
    }

    const float4* b4 = (const float4*)bias;
    float4* o4 = (float4*)(out + (size_t)n * F_DIM);
    #pragma unroll
    for (int j = 0; j < 8; j++) {
        int idx = j * 256 + tid;
        float4 b = b4[idx];
        float4 r;
        r.x = fmaxf(acc[j].x + b.x, 0.f);
        r.y = fmaxf(acc[j].y + b.y, 0.f);
        r.z = fmaxf(acc[j].z + b.z, 0.f);
        r.w = fmaxf(acc[j].w + b.w, 0.f);
        o4[idx] = r;
    }
}

// ---------------- readout ------------------------------------------------------
__global__ void nodedot_kernel(const float* __restrict__ hin,
                               const float* __restrict__ w)
{
    int n = blockIdx.x;
    int t = threadIdx.x;
    const float* hp = hin + (size_t)n * F_DIM;
    float s = 0.f;
    #pragma unroll 4
    for (int i = t; i < F_DIM; i += 256) s += hp[i] * w[i];
    __shared__ float sm[256];
    sm[t] = s;
    __syncthreads();
    for (int o = 128; o; o >>= 1) {
        if (t < o) sm[t] += sm[t + o];
        __syncthreads();
    }
    if (t == 0) g_nodeval[n] = sm[0];
}

__global__ void pool_kernel(const int* __restrict__ batch,
                            const float* __restrict__ lin_b,
                            float* __restrict__ out)
{
    __shared__ float ssum[G_GRAPHS];
    __shared__ int scnt[G_GRAPHS];
    int t = threadIdx.x;
    if (t < G_GRAPHS) { ssum[t] = 0.f; scnt[t] = 0; }
    __syncthreads();
    int g = batch[t];
    atomicAdd(&ssum[g], g_nodeval[t]);
    atomicAdd(&scnt[g], 1);
    __syncthreads();
    if (t < G_GRAPHS)
        out[t] = ssum[t] / fmaxf((float)scnt[t], 1.0f) + lin_b[0];
}

// ---------------- launch --------------------------------------------------------
extern "C" void kernel_launch(void* const* d_in, const int* in_sizes, int n_in,
                              void* d_out, int out_size)
{
    const float* x   = (const float*)d_in[0];
    const int*   ei  = (const int*)d_in[1];
    const int*   bat = (const int*)d_in[2];
    const float* W1  = (const float*)d_in[3];
    const float* as1 = (const float*)d_in[4];
    const float* ad1 = (const float*)d_in[5];
    const float* b1  = (const float*)d_in[6];
    const float* W2  = (const float*)d_in[7];
    const float* as2 = (const float*)d_in[8];
    const float* ad2 = (const float*)d_in[9];
    const float* b2  = (const float*)d_in[10];
    const float* lw  = (const float*)d_in[11];
    const float* lb  = (const float*)d_in[12];
    float* out = (float*)d_out;

    float *p_h = nullptr, *p_agg = nullptr;
    __nv_bfloat16 *p_Ah = nullptr, *p_Al = nullptr, *p_Bth = nullptr, *p_Btl = nullptr;
    cudaGetSymbolAddress((void**)&p_h, g_h);
    cudaGetSymbolAddress((void**)&p_agg, g_agg);
    cudaGetSymbolAddress((void**)&p_Ah, g_Ah);
    cudaGetSymbolAddress((void**)&p_Al, g_Al);
    cudaGetSymbolAddress((void**)&p_Bth, g_Bth);
    cudaGetSymbolAddress((void**)&p_Btl, g_Btl);

    cudaFuncSetAttribute(mma_gemm_kernel,
                         cudaFuncAttributeMaxDynamicSharedMemorySize, GEMM_SMEM);

    const int ethreads = 256;
    const int eblocks = (ET + ethreads - 1) / ethreads;

    // CSR build
    zero_cnt_kernel<<<1, N_NODES>>>();
    build_edges_kernel<<<eblocks, ethreads>>>(ei);
    scan_kernel<<<1, N_NODES>>>();
    scatter_kernel<<<eblocks, ethreads>>>();

    dim3 ggrid(F_DIM / 128, N_NODES / 128);   // (64, 8)
    dim3 tb32(32, 32);

    // ---- layer 1 ----
    convA_kernel<<<dim3((KP1 + 255) / 256, N_NODES), 256>>>(x, IN_DIM, KP1, p_Ah, p_Al);
    convBt_kernel<<<dim3(KP1 / 32, F_DIM / 32), tb32>>>(W1, IN_DIM, KP1, p_Bth, p_Btl);
    mma_gemm_kernel<<<ggrid, 256, GEMM_SMEM>>>(p_Ah, p_Al, p_Bth, p_Btl, p_h, KP1, KP1 / 32);
    scores_kernel<<<N_NODES, 512>>>(p_h, as1, ad1);
    attn_kernel<<<N_NODES, 512>>>();
    agg_kernel<<<N_NODES, 256>>>(p_h, b1, p_agg);

    // ---- layer 2 ----
    convA_kernel<<<dim3(F_DIM / 256, N_NODES), 256>>>(p_agg, F_DIM, F_DIM, p_Ah, p_Al);
    convBt_kernel<<<dim3(F_DIM / 32, F_DIM / 32), tb32>>>(W2, F_DIM, F_DIM, p_Bth, p_Btl);
    mma_gemm_kernel<<<ggrid, 256, GEMM_SMEM>>>(p_Ah, p_Al, p_Bth, p_Btl, p_h, F_DIM, F_DIM / 32);
    scores_kernel<<<N_NODES, 512>>>(p_h, as2, ad2);
    attn_kernel<<<N_NODES, 512>>>();
    agg_kernel<<<N_NODES, 256>>>(p_h, b2, p_agg);

    // ---- readout ----
    nodedot_kernel<<<N_NODES, 256>>>(p_agg, lw);
    pool_kernel<<<1, N_NODES>>>(bat, lb, out);
}

// round 10
// speedup vs baseline: 1.1662x; 1.1662x over previous
#include <cuda_runtime.h>
#include <cuda_bf16.h>
#include <cstdint>

#define N_NODES 1024
#define E_EDGES 16384
#define IN_DIM  1300
#define H_HEADS 16
#define D_HEAD  512
#define F_DIM   8192
#define G_GRAPHS 8
#define ET (E_EDGES + N_NODES)
#define SLOPE 0.2f

#define KP1 1344              // IN_DIM padded to multiple of 32

// ---------------- scratch ----------------------------------------------------
__device__ float g_h[N_NODES * F_DIM];
__device__ float g_agg[N_NODES * F_DIM];
__device__ float g_ssrc[N_NODES * H_HEADS];
__device__ float g_sdst[N_NODES * H_HEADS];
__device__ int   g_src[ET];
__device__ int   g_dst[ET];
__device__ int   g_cnt[N_NODES];
__device__ int   g_off[N_NODES + 1];
__device__ int   g_cur[N_NODES];
__device__ int   g_csr_src[ET];
__device__ float g_alpha[ET * H_HEADS];
__device__ float g_nodeval[N_NODES];
// bf16 split buffers (reused by both layers)
__device__ __nv_bfloat16 g_Ah[N_NODES * F_DIM];
__device__ __nv_bfloat16 g_Al[N_NODES * F_DIM];
__device__ __nv_bfloat16 g_Bth[(size_t)F_DIM * F_DIM];
__device__ __nv_bfloat16 g_Btl[(size_t)F_DIM * F_DIM];

// ---------------- PTX helpers ------------------------------------------------
__device__ __forceinline__ uint32_t smem_u32(const void* p) {
    uint32_t a;
    asm("{ .reg .u64 t; cvta.to.shared.u64 t, %1; cvt.u32.u64 %0, t; }" : "=r"(a) : "l"(p));
    return a;
}
__device__ __forceinline__ void cp16(uint32_t dst, const void* src) {
    asm volatile("cp.async.cg.shared.global [%0], [%1], 16;\n" :: "r"(dst), "l"(src) : "memory");
}
__device__ __forceinline__ void cp_commit() {
    asm volatile("cp.async.commit_group;\n" ::: "memory");
}
__device__ __forceinline__ void cp_wait0() { asm volatile("cp.async.wait_group 0;\n" ::: "memory"); }
__device__ __forceinline__ void cp_wait2() { asm volatile("cp.async.wait_group 2;\n" ::: "memory"); }

__device__ __forceinline__ void mma_bf16(float* c, const uint32_t* a, uint32_t b0, uint32_t b1) {
    asm volatile(
        "mma.sync.aligned.m16n8k16.row.col.f32.bf16.bf16.f32 "
        "{%0,%1,%2,%3}, {%4,%5,%6,%7}, {%8,%9}, {%0,%1,%2,%3};\n"
        : "+f"(c[0]), "+f"(c[1]), "+f"(c[2]), "+f"(c[3])
        : "r"(a[0]), "r"(a[1]), "r"(a[2]), "r"(a[3]), "r"(b0), "r"(b1));
}

__device__ __forceinline__ uint32_t lds32(uint32_t addr) {
    uint32_t v;
    asm volatile("ld.shared.b32 %0, [%1];" : "=r"(v) : "r"(addr));
    return v;
}

// fragment address within an 8KB [128 rows][32 bf16] tile with 16B-chunk XOR swizzle
__device__ __forceinline__ uint32_t frag_off(int row, int c, int t) {
    return (uint32_t)(row * 64 + ((c ^ ((row >> 1) & 3)) << 4) + (t << 2));
}

// ---------------- conversion kernels -----------------------------------------
__global__ void convA_kernel(const float* __restrict__ A, int K, int Kp,
                             __nv_bfloat16* __restrict__ Ah, __nv_bfloat16* __restrict__ Al)
{
    int row = blockIdx.y;
    int col = blockIdx.x * 256 + threadIdx.x;
    if (col >= Kp) return;
    float v = (col < K) ? A[(size_t)row * K + col] : 0.f;
    __nv_bfloat16 h = __float2bfloat16(v);
    float r = v - __bfloat162float(h);
    size_t o = (size_t)row * Kp + col;
    Ah[o] = h;
    Al[o] = __float2bfloat16(r);
}

// B [K, F_DIM] fp32 -> Bt_hi/lo [F_DIM, Kp] bf16 (transposed, zero-padded in K)
__global__ void convBt_kernel(const float* __restrict__ B, int K, int Kp,
                              __nv_bfloat16* __restrict__ Bth, __nv_bfloat16* __restrict__ Btl)
{
    __shared__ float sm[32][33];
    int k0 = blockIdx.x * 32, n0 = blockIdx.y * 32;
    int tx = threadIdx.x, ty = threadIdx.y;
    int k = k0 + ty;
    sm[ty][tx] = (k < K) ? B[(size_t)k * F_DIM + n0 + tx] : 0.f;
    __syncthreads();
    float v = sm[tx][ty];
    __nv_bfloat16 h = __float2bfloat16(v);
    size_t o = (size_t)(n0 + ty) * Kp + k0 + tx;
    Bth[o] = h;
    Btl[o] = __float2bfloat16(v - __bfloat162float(h));
}

// ---------------- mma.sync GEMM: C[1024, 8192] = A[1024,Kp] @ Bt[8192,Kp]^T ---
// CTA tile 128x128 with 128 threads (4 warps of 64x64), K-chunk 32, 3 stages.
// Stage layout (32KB): Ah[0,8K) Al[8K,16K) Bh[16K,24K) Bl[24K,32K)
#define STAGE_SZ 32768u
#define NSTAGE 3
#define GEMM_SMEM (STAGE_SZ * NSTAGE)

__global__ __launch_bounds__(128, 2) void mma_gemm_kernel(
    const __nv_bfloat16* __restrict__ Ah, const __nv_bfloat16* __restrict__ Al,
    const __nv_bfloat16* __restrict__ Bh, const __nv_bfloat16* __restrict__ Bl,
    float* __restrict__ C, int Kp, int nc)
{
    extern __shared__ __align__(128) char smem[];
    const uint32_t sb = smem_u32(smem);
    const int tid = threadIdx.x;
    const int wid = tid >> 5;      // 0..3
    const int lane = tid & 31;
    const int g = lane >> 2;       // 0..7
    const int t = lane & 3;        // 0..3
    const int wm = (wid >> 1) * 64;   // 0 or 64
    const int wn = (wid & 1) * 64;    // 0 or 64
    const int m0 = blockIdx.y * 128;
    const int n0 = blockIdx.x * 128;

    const __nv_bfloat16* aH = Ah + (size_t)m0 * Kp;
    const __nv_bfloat16* aL = Al + (size_t)m0 * Kp;
    const __nv_bfloat16* bH = Bh + (size_t)n0 * Kp;
    const __nv_bfloat16* bL = Bl + (size_t)n0 * Kp;

    float acc[4][8][4];
    #pragma unroll
    for (int i = 0; i < 4; i++)
        #pragma unroll
        for (int j = 0; j < 8; j++)
            #pragma unroll
            for (int q = 0; q < 4; q++) acc[i][j][q] = 0.f;

    // per-thread cp.async coords: 512 cp16 units per 8KB region, 4 per thread
    uint32_t so[4];
    int ru[4], chu[4];
    #pragma unroll
    for (int u = 0; u < 4; u++) {
        int uu = tid + u * 128;
        ru[u] = uu >> 2;
        chu[u] = uu & 3;
        so[u] = (uint32_t)(ru[u] * 64 + ((chu[u] ^ ((ru[u] >> 1) & 3)) << 4));
    }

    auto load_stage = [&](int c, int st) {
        const uint32_t base = sb + (uint32_t)st * STAGE_SZ;
        const int kc0 = c * 32;
        #pragma unroll
        for (int u = 0; u < 4; u++) {
            const size_t go = (size_t)ru[u] * Kp + kc0 + chu[u] * 8;
            cp16(base + so[u],          aH + go);
            cp16(base + 8192 + so[u],   aL + go);
            cp16(base + 16384 + so[u],  bH + go);
            cp16(base + 24576 + so[u],  bL + go);
        }
        cp_commit();
    };

    // precomputed fragment offsets for s=0 (s=1 flips bit5 via ^0x20)
    uint32_t aoff[4][4], boff[8][2];
    #pragma unroll
    for (int i = 0; i < 4; i++) {
        const int r0 = wm + i * 16 + g;
        const int r1 = r0 + 8;
        aoff[i][0] = frag_off(r0, 0, t);
        aoff[i][1] = frag_off(r1, 0, t);
        aoff[i][2] = frag_off(r0, 1, t);
        aoff[i][3] = frag_off(r1, 1, t);
    }
    #pragma unroll
    for (int j = 0; j < 8; j++) {
        const int n = wn + j * 8 + g;
        boff[j][0] = frag_off(n, 0, t);
        boff[j][1] = frag_off(n, 1, t);
    }

    load_stage(0, 0);
    if (nc > 1) load_stage(1, 1);

    for (int c = 0; c < nc; c++) {
        const int st = c % NSTAGE;
        if (c + 2 < nc) {
            load_stage(c + 2, (c + 2) % NSTAGE);
            cp_wait2();
        } else {
            cp_wait0();
        }
        __syncthreads();

        const uint32_t baseAh = sb + (uint32_t)st * STAGE_SZ;
        const uint32_t baseAl = baseAh + 8192;
        const uint32_t baseBh = baseAh + 16384;
        const uint32_t baseBl = baseAh + 24576;

        #pragma unroll
        for (int s = 0; s < 2; s++) {
            const uint32_t sx = (uint32_t)(s << 5);
            uint32_t ah[4][4], al[4][4];
            #pragma unroll
            for (int i = 0; i < 4; i++) {
                #pragma unroll
                for (int q = 0; q < 4; q++) {
                    ah[i][q] = lds32(baseAh + (aoff[i][q] ^ sx));
                    al[i][q] = lds32(baseAl + (aoff[i][q] ^ sx));
                }
            }
            #pragma unroll
            for (int j = 0; j < 8; j++) {
                const uint32_t bh0 = lds32(baseBh + (boff[j][0] ^ sx));
                const uint32_t bh1 = lds32(baseBh + (boff[j][1] ^ sx));
                const uint32_t bl0 = lds32(baseBl + (boff[j][0] ^ sx));
                const uint32_t bl1 = lds32(baseBl + (boff[j][1] ^ sx));
                #pragma unroll
                for (int i = 0; i < 4; i++) {
                    mma_bf16(acc[i][j], ah[i], bh0, bh1);
                    mma_bf16(acc[i][j], al[i], bh0, bh1);
                    mma_bf16(acc[i][j], ah[i], bl0, bl1);
                }
            }
        }
        __syncthreads();
    }

    // epilogue
    #pragma unroll
    for (int i = 0; i < 4; i++) {
        const int row0 = m0 + wm + i * 16 + g;
        #pragma unroll
        for (int j = 0; j < 8; j++) {
            const int col = n0 + wn + j * 8 + t * 2;
            float2* p0 = (float2*)(C + (size_t)row0 * F_DIM + col);
            float2* p1 = (float2*)(C + (size_t)(row0 + 8) * F_DIM + col);
            *p0 = make_float2(acc[i][j][0], acc[i][j][1]);
            *p1 = make_float2(acc[i][j][2], acc[i][j][3]);
        }
    }
}

// ---------------- attention scores ------------------------------------------
__global__ void scores_kernel(const float* __restrict__ h,
                              const float* __restrict__ asrc,
                              const float* __restrict__ adst)
{
    int n = blockIdx.x;
    int w = threadIdx.x >> 5;
    int lane = threadIdx.x & 31;
    const float* hp = h + (size_t)n * F_DIM + w * D_HEAD;
    const float* ap = asrc + w * D_HEAD;
    const float* bp = adst + w * D_HEAD;
    float s1 = 0.f, s2 = 0.f;
    #pragma unroll 4
    for (int d = lane; d < D_HEAD; d += 32) {
        float v = hp[d];
        s1 += v * ap[d];
        s2 += v * bp[d];
    }
    #pragma unroll
    for (int o = 16; o; o >>= 1) {
        s1 += __shfl_down_sync(0xffffffffu, s1, o);
        s2 += __shfl_down_sync(0xffffffffu, s2, o);
    }
    if (lane == 0) {
        g_ssrc[n * H_HEADS + w] = s1;
        g_sdst[n * H_HEADS + w] = s2;
    }
}

// ---------------- CSR build over dst -----------------------------------------
__global__ void zero_cnt_kernel() { g_cnt[threadIdx.x] = 0; }

__global__ void build_edges_kernel(const int* __restrict__ ei)
{
    int e = blockIdx.x * blockDim.x + threadIdx.x;
    if (e >= ET) return;
    int s, d;
    if (e < E_EDGES) { s = ei[e]; d = ei[E_EDGES + e]; }
    else             { s = e - E_EDGES; d = s; }
    g_src[e] = s;
    g_dst[e] = d;
    atomicAdd(&g_cnt[d], 1);
}

__global__ void scan_kernel()
{
    __shared__ int sm[N_NODES];
    int t = threadIdx.x;
    sm[t] = g_cnt[t];
    __syncthreads();
    for (int o = 1; o < N_NODES; o <<= 1) {
        int v = (t >= o) ? sm[t - o] : 0;
        __syncthreads();
        sm[t] += v;
        __syncthreads();
    }
    g_off[t + 1] = sm[t];
    int excl = (t == 0) ? 0 : sm[t - 1];
    if (t == 0) g_off[0] = 0;
    g_cur[t] = excl;
}

__global__ void scatter_kernel()
{
    int e = blockIdx.x * blockDim.x + threadIdx.x;
    if (e >= ET) return;
    int d = g_dst[e];
    int p = atomicAdd(&g_cur[d], 1);
    g_csr_src[p] = g_src[e];
}

// ---------------- segment softmax per (dst, head) ----------------------------
__global__ void attn_kernel()
{
    int n = blockIdx.x;
    int h = threadIdx.x >> 5;
    int lane = threadIdx.x & 31;
    int beg = g_off[n], end = g_off[n + 1];
    float sd = g_sdst[n * H_HEADS + h];

    float mx = -1e30f;
    for (int p = beg + lane; p < end; p += 32) {
        float e = g_ssrc[g_csr_src[p] * H_HEADS + h] + sd;
        e = (e > 0.f) ? e : SLOPE * e;
        mx = fmaxf(mx, e);
    }
    #pragma unroll
    for (int o = 16; o; o >>= 1)
        mx = fmaxf(mx, __shfl_xor_sync(0xffffffffu, mx, o));

    float sum = 0.f;
    for (int p = beg + lane; p < end; p += 32) {
        float e = g_ssrc[g_csr_src[p] * H_HEADS + h] + sd;
        e = (e > 0.f) ? e : SLOPE * e;
        float pv = __expf(e - mx);
        g_alpha[p * H_HEADS + h] = pv;
        sum += pv;
    }
    #pragma unroll
    for (int o = 16; o; o >>= 1)
        sum += __shfl_xor_sync(0xffffffffu, sum, o);

    float inv = 1.f / sum;
    for (int p = beg + lane; p < end; p += 32)
        g_alpha[p * H_HEADS + h] *= inv;
}

// ---------------- aggregation -------------------------------------------------
__global__ __launch_bounds__(256) void agg_kernel(
    const float* __restrict__ hin, const float* __restrict__ bias,
    float* __restrict__ out)
{
    int n = blockIdx.x;
    int tid = threadIdx.x;
    int hi = tid >> 7;
    int beg = g_off[n], end = g_off[n + 1];

    float4 acc[8];
    #pragma unroll
    for (int j = 0; j < 8; j++) acc[j] = make_float4(0.f, 0.f, 0.f, 0.f);

    for (int p = beg; p < end; p++) {
        int s = g_csr_src[p];
        const float4* hrow = (const float4*)(hin + (size_t)s * F_DIM);
        const float* al = &g_alpha[p * H_HEADS];
        #pragma unroll
        for (int j = 0; j < 8; j++) {
            float a = al[2 * j + hi];
            float4 v = hrow[j * 256 + tid];
            acc[j].x += a * v.x;
            acc[j].y += a * v.y;
            acc[j].z += a * v.z;
            acc[j].w += a * v.w;
        }
    }

    const float4* b4 = (const float4*)bias;
    float4* o4 = (float4*)(out + (size_t)n * F_DIM);
    #pragma unroll
    for (int j = 0; j < 8; j++) {
        int idx = j * 256 + tid;
        float4 b = b4[idx];
        float4 r;
        r.x = fmaxf(acc[j].x + b.x, 0.f);
        r.y = fmaxf(acc[j].y + b.y, 0.f);
        r.z = fmaxf(acc[j].z + b.z, 0.f);
        r.w = fmaxf(acc[j].w + b.w, 0.f);
        o4[idx] = r;
    }
}

// ---------------- readout ------------------------------------------------------
__global__ void nodedot_kernel(const float* __restrict__ hin,
                               const float* __restrict__ w)
{
    int n = blockIdx.x;
    int t = threadIdx.x;
    const float* hp = hin + (size_t)n * F_DIM;
    float s = 0.f;
    #pragma unroll 4
    for (int i = t; i < F_DIM; i += 256) s += hp[i] * w[i];
    __shared__ float sm[256];
    sm[t] = s;
    __syncthreads();
    for (int o = 128; o; o >>= 1) {
        if (t < o) sm[t] += sm[t + o];
        __syncthreads();
    }
    if (t == 0) g_nodeval[n] = sm[0];
}

__global__ void pool_kernel(const int* __restrict__ batch,
                            const float* __restrict__ lin_b,
                            float* __restrict__ out)
{
    __shared__ float ssum[G_GRAPHS];
    __shared__ int scnt[G_GRAPHS];
    int t = threadIdx.x;
    if (t < G_GRAPHS) { ssum[t] = 0.f; scnt[t] = 0; }
    __syncthreads();
    int g = batch[t];
    atomicAdd(&ssum[g], g_nodeval[t]);
    atomicAdd(&scnt[g], 1);
    __syncthreads();
    if (t < G_GRAPHS)
        out[t] = ssum[t] / fmaxf((float)scnt[t], 1.0f) + lin_b[0];
}

// ---------------- launch --------------------------------------------------------
extern "C" void kernel_launch(void* const* d_in, const int* in_sizes, int n_in,
                              void* d_out, int out_size)
{
    const float* x   = (const float*)d_in[0];
    const int*   ei  = (const int*)d_in[1];
    const int*   bat = (const int*)d_in[2];
    const float* W1  = (const float*)d_in[3];
    const float* as1 = (const float*)d_in[4];
    const float* ad1 = (const float*)d_in[5];
    const float* b1  = (const float*)d_in[6];
    const float* W2  = (const float*)d_in[7];
    const float* as2 = (const float*)d_in[8];
    const float* ad2 = (const float*)d_in[9];
    const float* b2  = (const float*)d_in[10];
    const float* lw  = (const float*)d_in[11];
    const float* lb  = (const float*)d_in[12];
    float* out = (float*)d_out;

    float *p_h = nullptr, *p_agg = nullptr;
    __nv_bfloat16 *p_Ah = nullptr, *p_Al = nullptr, *p_Bth = nullptr, *p_Btl = nullptr;
    cudaGetSymbolAddress((void**)&p_h, g_h);
    cudaGetSymbolAddress((void**)&p_agg, g_agg);
    cudaGetSymbolAddress((void**)&p_Ah, g_Ah);
    cudaGetSymbolAddress((void**)&p_Al, g_Al);
    cudaGetSymbolAddress((void**)&p_Bth, g_Bth);
    cudaGetSymbolAddress((void**)&p_Btl, g_Btl);

    cudaFuncSetAttribute(mma_gemm_kernel,
                         cudaFuncAttributeMaxDynamicSharedMemorySize, GEMM_SMEM);

    const int ethreads = 256;
    const int eblocks = (ET + ethreads - 1) / ethreads;

    // CSR build
    zero_cnt_kernel<<<1, N_NODES>>>();
    build_edges_kernel<<<eblocks, ethreads>>>(ei);
    scan_kernel<<<1, N_NODES>>>();
    scatter_kernel<<<eblocks, ethreads>>>();

    dim3 ggrid(F_DIM / 128, N_NODES / 128);   // (64, 8)
    dim3 tb32(32, 32);

    // ---- layer 1 ----
    convA_kernel<<<dim3((KP1 + 255) / 256, N_NODES), 256>>>(x, IN_DIM, KP1, p_Ah, p_Al);
    convBt_kernel<<<dim3(KP1 / 32, F_DIM / 32), tb32>>>(W1, IN_DIM, KP1, p_Bth, p_Btl);
    mma_gemm_kernel<<<ggrid, 128, GEMM_SMEM>>>(p_Ah, p_Al, p_Bth, p_Btl, p_h, KP1, KP1 / 32);
    scores_kernel<<<N_NODES, 512>>>(p_h, as1, ad1);
    attn_kernel<<<N_NODES, 512>>>();
    agg_kernel<<<N_NODES, 256>>>(p_h, b1, p_agg);

    // ---- layer 2 ----
    convA_kernel<<<dim3(F_DIM / 256, N_NODES), 256>>>(p_agg, F_DIM, F_DIM, p_Ah, p_Al);
    convBt_kernel<<<dim3(F_DIM / 32, F_DIM / 32), tb32>>>(W2, F_DIM, F_DIM, p_Bth, p_Btl);
    mma_gemm_kernel<<<ggrid, 128, GEMM_SMEM>>>(p_Ah, p_Al, p_Bth, p_Btl, p_h, F_DIM, F_DIM / 32);
    scores_kernel<<<N_NODES, 512>>>(p_h, as2, ad2);
    attn_kernel<<<N_NODES, 512>>>();
    agg_kernel<<<N_NODES, 256>>>(p_h, b2, p_agg);

    // ---- readout ----
    nodedot_kernel<<<N_NODES, 256>>>(p_agg, lw);
    pool_kernel<<<1, N_NODES>>>(bat, lb, out);
}

// round 11
// speedup vs baseline: 1.1724x; 1.0054x over previous
#include <cuda_runtime.h>
#include <cuda_bf16.h>
#include <cstdint>

#define N_NODES 1024
#define E_EDGES 16384
#define IN_DIM  1300
#define H_HEADS 16
#define D_HEAD  512
#define F_DIM   8192
#define G_GRAPHS 8
#define ET (E_EDGES + N_NODES)
#define SLOPE 0.2f

#define KP1 1344              // IN_DIM padded to multiple of 32

// ---------------- scratch ----------------------------------------------------
__device__ float g_h[N_NODES * F_DIM];
__device__ float g_agg[N_NODES * F_DIM];
__device__ float g_ssrc[N_NODES * H_HEADS];
__device__ float g_sdst[N_NODES * H_HEADS];
__device__ int   g_src[ET];
__device__ int   g_dst[ET];
__device__ int   g_cnt[N_NODES];
__device__ int   g_off[N_NODES + 1];
__device__ int   g_cur[N_NODES];
__device__ int   g_csr_src[ET];
__device__ float g_alpha[ET * H_HEADS];
__device__ float g_nodeval[N_NODES];
// bf16 split buffers (reused by both layers)
__device__ __nv_bfloat16 g_Ah[N_NODES * F_DIM];
__device__ __nv_bfloat16 g_Al[N_NODES * F_DIM];
__device__ __nv_bfloat16 g_Bth[(size_t)F_DIM * F_DIM];
__device__ __nv_bfloat16 g_Btl[(size_t)F_DIM * F_DIM];

// ---------------- PTX helpers ------------------------------------------------
__device__ __forceinline__ uint32_t smem_u32(const void* p) {
    uint32_t a;
    asm("{ .reg .u64 t; cvta.to.shared.u64 t, %1; cvt.u32.u64 %0, t; }" : "=r"(a) : "l"(p));
    return a;
}
__device__ __forceinline__ void cp16(uint32_t dst, const void* src) {
    asm volatile("cp.async.cg.shared.global [%0], [%1], 16;\n" :: "r"(dst), "l"(src) : "memory");
}
__device__ __forceinline__ void cp_commit() {
    asm volatile("cp.async.commit_group;\n" ::: "memory");
}
__device__ __forceinline__ void cp_wait0() { asm volatile("cp.async.wait_group 0;\n" ::: "memory"); }
__device__ __forceinline__ void cp_wait1() { asm volatile("cp.async.wait_group 1;\n" ::: "memory"); }

__device__ __forceinline__ void mma_bf16(float* c, const uint32_t* a, uint32_t b0, uint32_t b1) {
    asm volatile(
        "mma.sync.aligned.m16n8k16.row.col.f32.bf16.bf16.f32 "
        "{%0,%1,%2,%3}, {%4,%5,%6,%7}, {%8,%9}, {%0,%1,%2,%3};\n"
        : "+f"(c[0]), "+f"(c[1]), "+f"(c[2]), "+f"(c[3])
        : "r"(a[0]), "r"(a[1]), "r"(a[2]), "r"(a[3]), "r"(b0), "r"(b1));
}

__device__ __forceinline__ uint32_t lds32(uint32_t addr) {
    uint32_t v;
    asm volatile("ld.shared.b32 %0, [%1];" : "=r"(v) : "r"(addr));
    return v;
}

// fragment address within an 8KB [128 rows][32 bf16] tile with 16B-chunk XOR swizzle
__device__ __forceinline__ uint32_t frag_off(int row, int c, int t) {
    return (uint32_t)(row * 64 + ((c ^ ((row >> 1) & 3)) << 4) + (t << 2));
}

// ---------------- conversion kernels -----------------------------------------
__global__ void convA_kernel(const float* __restrict__ A, int K, int Kp,
                             __nv_bfloat16* __restrict__ Ah, __nv_bfloat16* __restrict__ Al)
{
    int row = blockIdx.y;
    int col = blockIdx.x * 256 + threadIdx.x;
    if (col >= Kp) return;
    float v = (col < K) ? A[(size_t)row * K + col] : 0.f;
    __nv_bfloat16 h = __float2bfloat16(v);
    float r = v - __bfloat162float(h);
    size_t o = (size_t)row * Kp + col;
    Ah[o] = h;
    Al[o] = __float2bfloat16(r);
}

// B [K, F_DIM] fp32 -> Bt_hi/lo [F_DIM, Kp] bf16 (transposed, zero-padded in K)
__global__ void convBt_kernel(const float* __restrict__ B, int K, int Kp,
                              __nv_bfloat16* __restrict__ Bth, __nv_bfloat16* __restrict__ Btl)
{
    __shared__ float sm[32][33];
    int k0 = blockIdx.x * 32, n0 = blockIdx.y * 32;
    int tx = threadIdx.x, ty = threadIdx.y;
    int k = k0 + ty;
    sm[ty][tx] = (k < K) ? B[(size_t)k * F_DIM + n0 + tx] : 0.f;
    __syncthreads();
    float v = sm[tx][ty];
    __nv_bfloat16 h = __float2bfloat16(v);
    size_t o = (size_t)(n0 + ty) * Kp + k0 + tx;
    Bth[o] = h;
    Btl[o] = __float2bfloat16(v - __bfloat162float(h));
}

// ---------------- mma.sync GEMM: C[1024, 8192] = A[1024,Kp] @ Bt[8192,Kp]^T ---
// CTA tile 128x128 with 128 threads (4 warps of 64x64), K-chunk 32, 3 stages.
// Stage layout (32KB): Ah[0,8K) Al[8K,16K) Bh[16K,24K) Bl[24K,32K)
#define STAGE_SZ 32768u
#define NSTAGE 3
#define GEMM_SMEM (STAGE_SZ * NSTAGE)

__global__ __launch_bounds__(128, 2) void mma_gemm_kernel(
    const __nv_bfloat16* __restrict__ Ah, const __nv_bfloat16* __restrict__ Al,
    const __nv_bfloat16* __restrict__ Bh, const __nv_bfloat16* __restrict__ Bl,
    float* __restrict__ C, int Kp, int nc)
{
    extern __shared__ __align__(128) char smem[];
    const uint32_t sb = smem_u32(smem);
    const int tid = threadIdx.x;
    const int wid = tid >> 5;      // 0..3
    const int lane = tid & 31;
    const int g = lane >> 2;       // 0..7
    const int t = lane & 3;        // 0..3
    const int wm = (wid >> 1) * 64;   // 0 or 64
    const int wn = (wid & 1) * 64;    // 0 or 64
    const int m0 = blockIdx.y * 128;
    const int n0 = blockIdx.x * 128;

    const __nv_bfloat16* aH = Ah + (size_t)m0 * Kp;
    const __nv_bfloat16* aL = Al + (size_t)m0 * Kp;
    const __nv_bfloat16* bH = Bh + (size_t)n0 * Kp;
    const __nv_bfloat16* bL = Bl + (size_t)n0 * Kp;

    float acc[4][8][4];
    #pragma unroll
    for (int i = 0; i < 4; i++)
        #pragma unroll
        for (int j = 0; j < 8; j++)
            #pragma unroll
            for (int q = 0; q < 4; q++) acc[i][j][q] = 0.f;

    // per-thread cp.async coords: 512 cp16 units per 8KB region, 4 per thread
    uint32_t so[4];
    int ru[4], chu[4];
    #pragma unroll
    for (int u = 0; u < 4; u++) {
        int uu = tid + u * 128;
        ru[u] = uu >> 2;
        chu[u] = uu & 3;
        so[u] = (uint32_t)(ru[u] * 64 + ((chu[u] ^ ((ru[u] >> 1) & 3)) << 4));
    }

    auto load_stage = [&](int c, int st) {
        const uint32_t base = sb + (uint32_t)st * STAGE_SZ;
        const int kc0 = c * 32;
        #pragma unroll
        for (int u = 0; u < 4; u++) {
            const size_t go = (size_t)ru[u] * Kp + kc0 + chu[u] * 8;
            cp16(base + so[u],          aH + go);
            cp16(base + 8192 + so[u],   aL + go);
            cp16(base + 16384 + so[u],  bH + go);
            cp16(base + 24576 + so[u],  bL + go);
        }
        cp_commit();
    };

    // precomputed fragment offsets for s=0 (s=1 flips bit5 via ^0x20)
    uint32_t aoff[4][4], boff[8][2];
    #pragma unroll
    for (int i = 0; i < 4; i++) {
        const int r0 = wm + i * 16 + g;
        const int r1 = r0 + 8;
        aoff[i][0] = frag_off(r0, 0, t);
        aoff[i][1] = frag_off(r1, 0, t);
        aoff[i][2] = frag_off(r0, 1, t);
        aoff[i][3] = frag_off(r1, 1, t);
    }
    #pragma unroll
    for (int j = 0; j < 8; j++) {
        const int n = wn + j * 8 + g;
        boff[j][0] = frag_off(n, 0, t);
        boff[j][1] = frag_off(n, 1, t);
    }

    load_stage(0, 0);
    if (nc > 1) load_stage(1, 1);

    for (int c = 0; c < nc; c++) {
        const int st = c % NSTAGE;
        // wait for chunk c's data (own thread), then one barrier: publishes
        // stage c to all threads AND fences compute(c-1) before the overwrite
        // of its stage by load(c+2) issued below.
        if (c + 1 < nc) cp_wait1(); else cp_wait0();
        __syncthreads();
        if (c + 2 < nc) load_stage(c + 2, (c + 2) % NSTAGE);

        const uint32_t baseAh = sb + (uint32_t)st * STAGE_SZ;
        const uint32_t baseAl = baseAh + 8192;
        const uint32_t baseBh = baseAh + 16384;
        const uint32_t baseBl = baseAh + 24576;

        #pragma unroll
        for (int s = 0; s < 2; s++) {
            const uint32_t sx = (uint32_t)(s << 5);
            uint32_t ah[4][4], al[4][4];
            #pragma unroll
            for (int i = 0; i < 4; i++) {
                #pragma unroll
                for (int q = 0; q < 4; q++) {
                    ah[i][q] = lds32(baseAh + (aoff[i][q] ^ sx));
                    al[i][q] = lds32(baseAl + (aoff[i][q] ^ sx));
                }
            }
            // B-fragment double buffer: prefetch j+1 during j's MMAs
            uint32_t bfr[2][4];
            bfr[0][0] = lds32(baseBh + (boff[0][0] ^ sx));
            bfr[0][1] = lds32(baseBh + (boff[0][1] ^ sx));
            bfr[0][2] = lds32(baseBl + (boff[0][0] ^ sx));
            bfr[0][3] = lds32(baseBl + (boff[0][1] ^ sx));
            #pragma unroll
            for (int j = 0; j < 8; j++) {
                const int cur = j & 1, nxt = cur ^ 1;
                if (j < 7) {
                    bfr[nxt][0] = lds32(baseBh + (boff[j + 1][0] ^ sx));
                    bfr[nxt][1] = lds32(baseBh + (boff[j + 1][1] ^ sx));
                    bfr[nxt][2] = lds32(baseBl + (boff[j + 1][0] ^ sx));
                    bfr[nxt][3] = lds32(baseBl + (boff[j + 1][1] ^ sx));
                }
                #pragma unroll
                for (int i = 0; i < 4; i++) {
                    mma_bf16(acc[i][j], ah[i], bfr[cur][0], bfr[cur][1]);
                    mma_bf16(acc[i][j], al[i], bfr[cur][0], bfr[cur][1]);
                    mma_bf16(acc[i][j], ah[i], bfr[cur][2], bfr[cur][3]);
                }
            }
        }
    }

    // epilogue
    #pragma unroll
    for (int i = 0; i < 4; i++) {
        const int row0 = m0 + wm + i * 16 + g;
        #pragma unroll
        for (int j = 0; j < 8; j++) {
            const int col = n0 + wn + j * 8 + t * 2;
            float2* p0 = (float2*)(C + (size_t)row0 * F_DIM + col);
            float2* p1 = (float2*)(C + (size_t)(row0 + 8) * F_DIM + col);
            *p0 = make_float2(acc[i][j][0], acc[i][j][1]);
            *p1 = make_float2(acc[i][j][2], acc[i][j][3]);
        }
    }
}

// ---------------- attention scores ------------------------------------------
__global__ void scores_kernel(const float* __restrict__ h,
                              const float* __restrict__ asrc,
                              const float* __restrict__ adst)
{
    int n = blockIdx.x;
    int w = threadIdx.x >> 5;
    int lane = threadIdx.x & 31;
    const float* hp = h + (size_t)n * F_DIM + w * D_HEAD;
    const float* ap = asrc + w * D_HEAD;
    const float* bp = adst + w * D_HEAD;
    float s1 = 0.f, s2 = 0.f;
    #pragma unroll 4
    for (int d = lane; d < D_HEAD; d += 32) {
        float v = hp[d];
        s1 += v * ap[d];
        s2 += v * bp[d];
    }
    #pragma unroll
    for (int o = 16; o; o >>= 1) {
        s1 += __shfl_down_sync(0xffffffffu, s1, o);
        s2 += __shfl_down_sync(0xffffffffu, s2, o);
    }
    if (lane == 0) {
        g_ssrc[n * H_HEADS + w] = s1;
        g_sdst[n * H_HEADS + w] = s2;
    }
}

// ---------------- CSR build over dst -----------------------------------------
__global__ void zero_cnt_kernel() { g_cnt[threadIdx.x] = 0; }

__global__ void build_edges_kernel(const int* __restrict__ ei)
{
    int e = blockIdx.x * blockDim.x + threadIdx.x;
    if (e >= ET) return;
    int s, d;
    if (e < E_EDGES) { s = ei[e]; d = ei[E_EDGES + e]; }
    else             { s = e - E_EDGES; d = s; }
    g_src[e] = s;
    g_dst[e] = d;
    atomicAdd(&g_cnt[d], 1);
}

__global__ void scan_kernel()
{
    __shared__ int sm[N_NODES];
    int t = threadIdx.x;
    sm[t] = g_cnt[t];
    __syncthreads();
    for (int o = 1; o < N_NODES; o <<= 1) {
        int v = (t >= o) ? sm[t - o] : 0;
        __syncthreads();
        sm[t] += v;
        __syncthreads();
    }
    g_off[t + 1] = sm[t];
    int excl = (t == 0) ? 0 : sm[t - 1];
    if (t == 0) g_off[0] = 0;
    g_cur[t] = excl;
}

__global__ void scatter_kernel()
{
    int e = blockIdx.x * blockDim.x + threadIdx.x;
    if (e >= ET) return;
    int d = g_dst[e];
    int p = atomicAdd(&g_cur[d], 1);
    g_csr_src[p] = g_src[e];
}

// ---------------- segment softmax per (dst, head) ----------------------------
__global__ void attn_kernel()
{
    int n = blockIdx.x;
    int h = threadIdx.x >> 5;
    int lane = threadIdx.x & 31;
    int beg = g_off[n], end = g_off[n + 1];
    float sd = g_sdst[n * H_HEADS + h];

    float mx = -1e30f;
    for (int p = beg + lane; p < end; p += 32) {
        float e = g_ssrc[g_csr_src[p] * H_HEADS + h] + sd;
        e = (e > 0.f) ? e : SLOPE * e;
        mx = fmaxf(mx, e);
    }
    #pragma unroll
    for (int o = 16; o; o >>= 1)
        mx = fmaxf(mx, __shfl_xor_sync(0xffffffffu, mx, o));

    float sum = 0.f;
    for (int p = beg + lane; p < end; p += 32) {
        float e = g_ssrc[g_csr_src[p] * H_HEADS + h] + sd;
        e = (e > 0.f) ? e : SLOPE * e;
        float pv = __expf(e - mx);
        g_alpha[p * H_HEADS + h] = pv;
        sum += pv;
    }
    #pragma unroll
    for (int o = 16; o; o >>= 1)
        sum += __shfl_xor_sync(0xffffffffu, sum, o);

    float inv = 1.f / sum;
    for (int p = beg + lane; p < end; p += 32)
        g_alpha[p * H_HEADS + h] *= inv;
}

// ---------------- aggregation -------------------------------------------------
__global__ __launch_bounds__(256) void agg_kernel(
    const float* __restrict__ hin, const float* __restrict__ bias,
    float* __restrict__ out)
{
    int n = blockIdx.x;
    int tid = threadIdx.x;
    int hi = tid >> 7;
    int beg = g_off[n], end = g_off[n + 1];

    float4 acc[8];
    #pragma unroll
    for (int j = 0; j < 8; j++) acc[j] = make_float4(0.f, 0.f, 0.f, 0.f);

    for (int p = beg; p < end; p++) {
        int s = g_csr_src[p];
        const float4* hrow = (const float4*)(hin + (size_t)s * F_DIM);
        const float* al = &g_alpha[p * H_HEADS];
        #pragma unroll
        for (int j = 0; j < 8; j++) {
            float a = al[2 * j + hi];
            float4 v = hrow[j * 256 + tid];
            acc[j].x += a * v.x;
            acc[j].y += a * v.y;
            acc[j].z += a * v.z;
            acc[j].w += a * v.w;
        }
    }

    const float4* b4 = (const float4*)bias;
    float4* o4 = (float4*)(out + (size_t)n * F_DIM);
    #pragma unroll
    for (int j = 0; j < 8; j++) {
        int idx = j * 256 + tid;
        float4 b = b4[idx];
        float4 r;
        r.x = fmaxf(acc[j].x + b.x, 0.f);
        r.y = fmaxf(acc[j].y + b.y, 0.f);
        r.z = fmaxf(acc[j].z + b.z, 0.f);
        r.w = fmaxf(acc[j].w + b.w, 0.f);
        o4[idx] = r;
    }
}

// ---------------- readout ------------------------------------------------------
__global__ void nodedot_kernel(const float* __restrict__ hin,
                               const float* __restrict__ w)
{
    int n = blockIdx.x;
    int t = threadIdx.x;
    const float* hp = hin + (size_t)n * F_DIM;
    float s = 0.f;
    #pragma unroll 4
    for (int i = t; i < F_DIM; i += 256) s += hp[i] * w[i];
    __shared__ float sm[256];
    sm[t] = s;
    __syncthreads();
    for (int o = 128; o; o >>= 1) {
        if (t < o) sm[t] += sm[t + o];
        __syncthreads();
    }
    if (t == 0) g_nodeval[n] = sm[0];
}

__global__ void pool_kernel(const int* __restrict__ batch,
                            const float* __restrict__ lin_b,
                            float* __restrict__ out)
{
    __shared__ float ssum[G_GRAPHS];
    __shared__ int scnt[G_GRAPHS];
    int t = threadIdx.x;
    if (t < G_GRAPHS) { ssum[t] = 0.f; scnt[t] = 0; }
    __syncthreads();
    int g = batch[t];
    atomicAdd(&ssum[g], g_nodeval[t]);
    atomicAdd(&scnt[g], 1);
    __syncthreads();
    if (t < G_GRAPHS)
        out[t] = ssum[t] / fmaxf((float)scnt[t], 1.0f) + lin_b[0];
}

// ---------------- launch --------------------------------------------------------
extern "C" void kernel_launch(void* const* d_in, const int* in_sizes, int n_in,
                              void* d_out, int out_size)
{
    const float* x   = (const float*)d_in[0];
    const int*   ei  = (const int*)d_in[1];
    const int*   bat = (const int*)d_in[2];
    const float* W1  = (const float*)d_in[3];
    const float* as1 = (const float*)d_in[4];
    const float* ad1 = (const float*)d_in[5];
    const float* b1  = (const float*)d_in[6];
    const float* W2  = (const float*)d_in[7];
    const float* as2 = (const float*)d_in[8];
    const float* ad2 = (const float*)d_in[9];
    const float* b2  = (const float*)d_in[10];
    const float* lw  = (const float*)d_in[11];
    const float* lb  = (const float*)d_in[12];
    float* out = (float*)d_out;

    float *p_h = nullptr, *p_agg = nullptr;
    __nv_bfloat16 *p_Ah = nullptr, *p_Al = nullptr, *p_Bth = nullptr, *p_Btl = nullptr;
    cudaGetSymbolAddress((void**)&p_h, g_h);
    cudaGetSymbolAddress((void**)&p_agg, g_agg);
    cudaGetSymbolAddress((void**)&p_Ah, g_Ah);
    cudaGetSymbolAddress((void**)&p_Al, g_Al);
    cudaGetSymbolAddress((void**)&p_Bth, g_Bth);
    cudaGetSymbolAddress((void**)&p_Btl, g_Btl);

    cudaFuncSetAttribute(mma_gemm_kernel,
                         cudaFuncAttributeMaxDynamicSharedMemorySize, GEMM_SMEM);

    const int ethreads = 256;
    const int eblocks = (ET + ethreads - 1) / ethreads;

    // CSR build
    zero_cnt_kernel<<<1, N_NODES>>>();
    build_edges_kernel<<<eblocks, ethreads>>>(ei);
    scan_kernel<<<1, N_NODES>>>();
    scatter_kernel<<<eblocks, ethreads>>>();

    dim3 ggrid(F_DIM / 128, N_NODES / 128);   // (64, 8)
    dim3 tb32(32, 32);

    // ---- layer 1 ----
    convA_kernel<<<dim3((KP1 + 255) / 256, N_NODES), 256>>>(x, IN_DIM, KP1, p_Ah, p_Al);
    convBt_kernel<<<dim3(KP1 / 32, F_DIM / 32), tb32>>>(W1, IN_DIM, KP1, p_Bth, p_Btl);
    mma_gemm_kernel<<<ggrid, 128, GEMM_SMEM>>>(p_Ah, p_Al, p_Bth, p_Btl, p_h, KP1, KP1 / 32);
    scores_kernel<<<N_NODES, 512>>>(p_h, as1, ad1);
    attn_kernel<<<N_NODES, 512>>>();
    agg_kernel<<<N_NODES, 256>>>(p_h, b1, p_agg);

    // ---- layer 2 ----
    convA_kernel<<<dim3(F_DIM / 256, N_NODES), 256>>>(p_agg, F_DIM, F_DIM, p_Ah, p_Al);
    convBt_kernel<<<dim3(F_DIM / 32, F_DIM / 32), tb32>>>(W2, F_DIM, F_DIM, p_Bth, p_Btl);
    mma_gemm_kernel<<<ggrid, 128, GEMM_SMEM>>>(p_Ah, p_Al, p_Bth, p_Btl, p_h, F_DIM, F_DIM / 32);
    scores_kernel<<<N_NODES, 512>>>(p_h, as2, ad2);
    attn_kernel<<<N_NODES, 512>>>();
    agg_kernel<<<N_NODES, 256>>>(p_h, b2, p_agg);

    // ---- readout ----
    nodedot_kernel<<<N_NODES, 256>>>(p_agg, lw);
    pool_kernel<<<1, N_NODES>>>(bat, lb, out);
}

// round 15
// speedup vs baseline: 1.5207x; 1.2971x over previous
#include <cuda_runtime.h>
#include <cuda_fp16.h>
#include <cstdint>

#define N_NODES 1024
#define E_EDGES 16384
#define IN_DIM  1300
#define H_HEADS 16
#define D_HEAD  512
#define F_DIM   8192
#define G_GRAPHS 8
#define ET (E_EDGES + N_NODES)
#define SLOPE 0.2f

#define KP1 1344              // IN_DIM padded to multiple of 32

// ---------------- scratch ----------------------------------------------------
__device__ float g_h[N_NODES * F_DIM];
__device__ float g_agg[N_NODES * F_DIM];
__device__ float g_ssrc[N_NODES * H_HEADS];
__device__ float g_sdst[N_NODES * H_HEADS];
__device__ int   g_src[ET];
__device__ int   g_dst[ET];
__device__ int   g_cnt[N_NODES];
__device__ int   g_off[N_NODES + 1];
__device__ int   g_cur[N_NODES];
__device__ int   g_csr_src[ET];
__device__ float g_alpha[ET * H_HEADS];
__device__ float g_nodeval[N_NODES];
// fp16 split buffers (reused by both layers)
__device__ __half g_Ah[N_NODES * F_DIM];
__device__ __half g_Al[N_NODES * F_DIM];
__device__ __half g_Bth[(size_t)F_DIM * F_DIM];

// ---------------- PTX helpers ------------------------------------------------
__device__ __forceinline__ uint32_t smem_u32(const void* p) {
    uint32_t a;
    asm("{ .reg .u64 t; cvta.to.shared.u64 t, %1; cvt.u32.u64 %0, t; }" : "=r"(a) : "l"(p));
    return a;
}
__device__ __forceinline__ void cp16(uint32_t dst, const void* src) {
    asm volatile("cp.async.cg.shared.global [%0], [%1], 16;\n" :: "r"(dst), "l"(src) : "memory");
}
__device__ __forceinline__ void cp_commit() {
    asm volatile("cp.async.commit_group;\n" ::: "memory");
}
__device__ __forceinline__ void cp_wait0() { asm volatile("cp.async.wait_group 0;\n" ::: "memory"); }
__device__ __forceinline__ void cp_wait1() { asm volatile("cp.async.wait_group 1;\n" ::: "memory"); }

__device__ __forceinline__ void mma_f16(float* c, const uint32_t* a, uint32_t b0, uint32_t b1) {
    asm volatile(
        "mma.sync.aligned.m16n8k16.row.col.f32.f16.f16.f32 "
        "{%0,%1,%2,%3}, {%4,%5,%6,%7}, {%8,%9}, {%0,%1,%2,%3};\n"
        : "+f"(c[0]), "+f"(c[1]), "+f"(c[2]), "+f"(c[3])
        : "r"(a[0]), "r"(a[1]), "r"(a[2]), "r"(a[3]), "r"(b0), "r"(b1));
}

__device__ __forceinline__ uint32_t lds32(uint32_t addr) {
    uint32_t v;
    asm volatile("ld.shared.b32 %0, [%1];" : "=r"(v) : "r"(addr));
    return v;
}

// fragment address within an 8KB [128 rows][32 fp16] tile with 16B-chunk XOR swizzle
__device__ __forceinline__ uint32_t frag_off(int row, int c, int t) {
    return (uint32_t)(row * 64 + ((c ^ ((row >> 1) & 3)) << 4) + (t << 2));
}

// ---------------- conversion kernels -----------------------------------------
__global__ void convA_kernel(const float* __restrict__ A, int K, int Kp,
                             __half* __restrict__ Ah, __half* __restrict__ Al)
{
    int row = blockIdx.y;
    int col = blockIdx.x * 256 + threadIdx.x;
    if (col >= Kp) return;
    float v = (col < K) ? A[(size_t)row * K + col] : 0.f;
    __half h = __float2half_rn(v);
    float r = v - __half2float(h);
    size_t o = (size_t)row * Kp + col;
    Ah[o] = h;
    Al[o] = __float2half_rn(r);
}

// B [K, F_DIM] fp32 -> Bt [F_DIM, Kp] fp16 (transposed, zero-padded in K)
__global__ void convBt_kernel(const float* __restrict__ B, int K, int Kp,
                              __half* __restrict__ Bth)
{
    __shared__ float sm[32][33];
    int k0 = blockIdx.x * 32, n0 = blockIdx.y * 32;
    int tx = threadIdx.x, ty = threadIdx.y;
    int k = k0 + ty;
    sm[ty][tx] = (k < K) ? B[(size_t)k * F_DIM + n0 + tx] : 0.f;
    __syncthreads();
    float v = sm[tx][ty];
    Bth[(size_t)(n0 + ty) * Kp + k0 + tx] = __float2half_rn(v);
}

// ---------------- mma.sync GEMM: C[1024, 8192] = A[1024,Kp] @ Bt[8192,Kp]^T ---
// CTA tile 128x128 with 128 threads (4 warps of 64x64), K-chunk 32, 3 stages.
// Stage layout (24KB): Ah[0,8K) Al[8K,16K) Bh[16K,24K)
#define STAGE_SZ 24576u
#define NSTAGE 3
#define GEMM_SMEM (STAGE_SZ * NSTAGE)

__global__ __launch_bounds__(128, 2) void mma_gemm_kernel(
    const __half* __restrict__ Ah, const __half* __restrict__ Al,
    const __half* __restrict__ Bh,
    float* __restrict__ C, int Kp, int nc)
{
    extern __shared__ __align__(128) char smem[];
    const uint32_t sb = smem_u32(smem);
    const int tid = threadIdx.x;
    const int wid = tid >> 5;      // 0..3
    const int lane = tid & 31;
    const int g = lane >> 2;       // 0..7
    const int t = lane & 3;        // 0..3
    const int wm = (wid >> 1) * 64;   // 0 or 64
    const int wn = (wid & 1) * 64;    // 0 or 64
    const int m0 = blockIdx.y * 128;
    const int n0 = blockIdx.x * 128;

    const __half* aH = Ah + (size_t)m0 * Kp;
    const __half* aL = Al + (size_t)m0 * Kp;
    const __half* bH = Bh + (size_t)n0 * Kp;

    float acc[4][8][4];
    #pragma unroll
    for (int i = 0; i < 4; i++)
        #pragma unroll
        for (int j = 0; j < 8; j++)
            #pragma unroll
            for (int q = 0; q < 4; q++) acc[i][j][q] = 0.f;

    // per-thread cp.async coords: 512 cp16 units per 8KB region, 4 per thread
    uint32_t so[4];
    int ru[4], chu[4];
    #pragma unroll
    for (int u = 0; u < 4; u++) {
        int uu = tid + u * 128;
        ru[u] = uu >> 2;
        chu[u] = uu & 3;
        so[u] = (uint32_t)(ru[u] * 64 + ((chu[u] ^ ((ru[u] >> 1) & 3)) << 4));
    }

    auto load_stage = [&](int c, int st) {
        const uint32_t base = sb + (uint32_t)st * STAGE_SZ;
        const int kc0 = c * 32;
        #pragma unroll
        for (int u = 0; u < 4; u++) {
            const size_t go = (size_t)ru[u] * Kp + kc0 + chu[u] * 8;
            cp16(base + so[u],          aH + go);
            cp16(base + 8192 + so[u],   aL + go);
            cp16(base + 16384 + so[u],  bH + go);
        }
        cp_commit();
    };

    // precomputed fragment offsets for s=0 (s=1 flips bit5 via ^0x20)
    uint32_t aoff[4][4], boff[8][2];
    #pragma unroll
    for (int i = 0; i < 4; i++) {
        const int r0 = wm + i * 16 + g;
        const int r1 = r0 + 8;
        aoff[i][0] = frag_off(r0, 0, t);
        aoff[i][1] = frag_off(r1, 0, t);
        aoff[i][2] = frag_off(r0, 1, t);
        aoff[i][3] = frag_off(r1, 1, t);
    }
    #pragma unroll
    for (int j = 0; j < 8; j++) {
        const int n = wn + j * 8 + g;
        boff[j][0] = frag_off(n, 0, t);
        boff[j][1] = frag_off(n, 1, t);
    }

    load_stage(0, 0);
    if (nc > 1) load_stage(1, 1);

    for (int c = 0; c < nc; c++) {
        const int st = c % NSTAGE;
        if (c + 1 < nc) cp_wait1(); else cp_wait0();
        __syncthreads();
        if (c + 2 < nc) load_stage(c + 2, (c + 2) % NSTAGE);

        const uint32_t baseAh = sb + (uint32_t)st * STAGE_SZ;
        const uint32_t baseAl = baseAh + 8192;
        const uint32_t baseBh = baseAh + 16384;

        #pragma unroll
        for (int s = 0; s < 2; s++) {
            const uint32_t sx = (uint32_t)(s << 5);
            uint32_t ah[4][4], al[4][4];
            #pragma unroll
            for (int i = 0; i < 4; i++) {
                #pragma unroll
                for (int q = 0; q < 4; q++) {
                    ah[i][q] = lds32(baseAh + (aoff[i][q] ^ sx));
                    al[i][q] = lds32(baseAl + (aoff[i][q] ^ sx));
                }
            }
            // B-fragment double buffer: prefetch j+1 during j's MMAs
            uint32_t bfr[2][2];
            bfr[0][0] = lds32(baseBh + (boff[0][0] ^ sx));
            bfr[0][1] = lds32(baseBh + (boff[0][1] ^ sx));
            #pragma unroll
            for (int j = 0; j < 8; j++) {
                const int cur = j & 1, nxt = cur ^ 1;
                if (j < 7) {
                    bfr[nxt][0] = lds32(baseBh + (boff[j + 1][0] ^ sx));
                    bfr[nxt][1] = lds32(baseBh + (boff[j + 1][1] ^ sx));
                }
                #pragma unroll
                for (int i = 0; i < 4; i++) {
                    mma_f16(acc[i][j], ah[i], bfr[cur][0], bfr[cur][1]);
                    mma_f16(acc[i][j], al[i], bfr[cur][0], bfr[cur][1]);
                }
            }
        }
    }

    // epilogue
    #pragma unroll
    for (int i = 0; i < 4; i++) {
        const int row0 = m0 + wm + i * 16 + g;
        #pragma unroll
        for (int j = 0; j < 8; j++) {
            const int col = n0 + wn + j * 8 + t * 2;
            float2* p0 = (float2*)(C + (size_t)row0 * F_DIM + col);
            float2* p1 = (float2*)(C + (size_t)(row0 + 8) * F_DIM + col);
            *p0 = make_float2(acc[i][j][0], acc[i][j][1]);
            *p1 = make_float2(acc[i][j][2], acc[i][j][3]);
        }
    }
}

// ---------------- attention scores ------------------------------------------
__global__ void scores_kernel(const float* __restrict__ h,
                              const float* __restrict__ asrc,
                              const float* __restrict__ adst)
{
    int n = blockIdx.x;
    int w = threadIdx.x >> 5;
    int lane = threadIdx.x & 31;
    const float* hp = h + (size_t)n * F_DIM + w * D_HEAD;
    const float* ap = asrc + w * D_HEAD;
    const float* bp = adst + w * D_HEAD;
    float s1 = 0.f, s2 = 0.f;
    #pragma unroll 4
    for (int d = lane; d < D_HEAD; d += 32) {
        float v = hp[d];
        s1 += v * ap[d];
        s2 += v * bp[d];
    }
    #pragma unroll
    for (int o = 16; o; o >>= 1) {
        s1 += __shfl_down_sync(0xffffffffu, s1, o);
        s2 += __shfl_down_sync(0xffffffffu, s2, o);
    }
    if (lane == 0) {
        g_ssrc[n * H_HEADS + w] = s1;
        g_sdst[n * H_HEADS + w] = s2;
    }
}

// ---------------- CSR build over dst -----------------------------------------
__global__ void zero_cnt_kernel() { g_cnt[threadIdx.x] = 0; }

__global__ void build_edges_kernel(const int* __restrict__ ei)
{
    int e = blockIdx.x * blockDim.x + threadIdx.x;
    if (e >= ET) return;
    int s, d;
    if (e < E_EDGES) { s = ei[e]; d = ei[E_EDGES + e]; }
    else             { s = e - E_EDGES; d = s; }
    g_src[e] = s;
    g_dst[e] = d;
    atomicAdd(&g_cnt[d], 1);
}

__global__ void scan_kernel()
{
    __shared__ int sm[N_NODES];
    int t = threadIdx.x;
    sm[t] = g_cnt[t];
    __syncthreads();
    for (int o = 1; o < N_NODES; o <<= 1) {
        int v = (t >= o) ? sm[t - o] : 0;
        __syncthreads();
        sm[t] += v;
        __syncthreads();
    }
    g_off[t + 1] = sm[t];
    int excl = (t == 0) ? 0 : sm[t - 1];
    if (t == 0) g_off[0] = 0;
    g_cur[t] = excl;
}

__global__ void scatter_kernel()
{
    int e = blockIdx.x * blockDim.x + threadIdx.x;
    if (e >= ET) return;
    int d = g_dst[e];
    int p = atomicAdd(&g_cur[d], 1);
    g_csr_src[p] = g_src[e];
}

// ---------------- segment softmax per (dst, head) ----------------------------
__global__ void attn_kernel()
{
    int n = blockIdx.x;
    int h = threadIdx.x >> 5;
    int lane = threadIdx.x & 31;
    int beg = g_off[n], end = g_off[n + 1];
    float sd = g_sdst[n * H_HEADS + h];

    float mx = -1e30f;
    for (int p = beg + lane; p < end; p += 32) {
        float e = g_ssrc[g_csr_src[p] * H_HEADS + h] + sd;
        e = (e > 0.f) ? e : SLOPE * e;
        mx = fmaxf(mx, e);
    }
    #pragma unroll
    for (int o = 16; o; o >>= 1)
        mx = fmaxf(mx, __shfl_xor_sync(0xffffffffu, mx, o));

    float sum = 0.f;
    for (int p = beg + lane; p < end; p += 32) {
        float e = g_ssrc[g_csr_src[p] * H_HEADS + h] + sd;
        e = (e > 0.f) ? e : SLOPE * e;
        float pv = __expf(e - mx);
        g_alpha[p * H_HEADS + h] = pv;
        sum += pv;
    }
    #pragma unroll
    for (int o = 16; o; o >>= 1)
        sum += __shfl_xor_sync(0xffffffffu, sum, o);

    float inv = 1.f / sum;
    for (int p = beg + lane; p < end; p += 32)
        g_alpha[p * H_HEADS + h] *= inv;
}

// ---------------- aggregation -------------------------------------------------
__global__ __launch_bounds__(256) void agg_kernel(
    const float* __restrict__ hin, const float* __restrict__ bias,
    float* __restrict__ out)
{
    int n = blockIdx.x;
    int tid = threadIdx.x;
    int hi = tid >> 7;
    int beg = g_off[n], end = g_off[n + 1];

    float4 acc[8];
    #pragma unroll
    for (int j = 0; j < 8; j++) acc[j] = make_float4(0.f, 0.f, 0.f, 0.f);

    for (int p = beg; p < end; p++) {
        int s = g_csr_src[p];
        const float4* hrow = (const float4*)(hin + (size_t)s * F_DIM);
        const float* al = &g_alpha[p * H_HEADS];
        #pragma unroll
        for (int j = 0; j < 8; j++) {
            float a = al[2 * j + hi];
            float4 v = hrow[j * 256 + tid];
            acc[j].x += a * v.x;
            acc[j].y += a * v.y;
            acc[j].z += a * v.z;
            acc[j].w += a * v.w;
        }
    }

    const float4* b4 = (const float4*)bias;
    float4* o4 = (float4*)(out + (size_t)n * F_DIM);
    #pragma unroll
    for (int j = 0; j < 8; j++) {
        int idx = j * 256 + tid;
        float4 b = b4[idx];
        float4 r;
        r.x = fmaxf(acc[j].x + b.x, 0.f);
        r.y = fmaxf(acc[j].y + b.y, 0.f);
        r.z = fmaxf(acc[j].z + b.z, 0.f);
        r.w = fmaxf(acc[j].w + b.w, 0.f);
        o4[idx] = r;
    }
}

// ---------------- readout ------------------------------------------------------
__global__ void nodedot_kernel(const float* __restrict__ hin,
                               const float* __restrict__ w)
{
    int n = blockIdx.x;
    int t = threadIdx.x;
    const float* hp = hin + (size_t)n * F_DIM;
    float s = 0.f;
    #pragma unroll 4
    for (int i = t; i < F_DIM; i += 256) s += hp[i] * w[i];
    __shared__ float sm[256];
    sm[t] = s;
    __syncthreads();
    for (int o = 128; o; o >>= 1) {
        if (t < o) sm[t] += sm[t + o];
        __syncthreads();
    }
    if (t == 0) g_nodeval[n] = sm[0];
}

__global__ void pool_kernel(const int* __restrict__ batch,
                            const float* __restrict__ lin_b,
                            float* __restrict__ out)
{
    __shared__ float ssum[G_GRAPHS];
    __shared__ int scnt[G_GRAPHS];
    int t = threadIdx.x;
    if (t < G_GRAPHS) { ssum[t] = 0.f; scnt[t] = 0; }
    __syncthreads();
    int g = batch[t];
    atomicAdd(&ssum[g], g_nodeval[t]);
    atomicAdd(&scnt[g], 1);
    __syncthreads();
    if (t < G_GRAPHS)
        out[t] = ssum[t] / fmaxf((float)scnt[t], 1.0f) + lin_b[0];
}

// ---------------- launch --------------------------------------------------------
extern "C" void kernel_launch(void* const* d_in, const int* in_sizes, int n_in,
                              void* d_out, int out_size)
{
    const float* x   = (const float*)d_in[0];
    const int*   ei  = (const int*)d_in[1];
    const int*   bat = (const int*)d_in[2];
    const float* W1  = (const float*)d_in[3];
    const float* as1 = (const float*)d_in[4];
    const float* ad1 = (const float*)d_in[5];
    const float* b1  = (const float*)d_in[6];
    const float* W2  = (const float*)d_in[7];
    const float* as2 = (const float*)d_in[8];
    const float* ad2 = (const float*)d_in[9];
    const float* b2  = (const float*)d_in[10];
    const float* lw  = (const float*)d_in[11];
    const float* lb  = (const float*)d_in[12];
    float* out = (float*)d_out;

    float *p_h = nullptr, *p_agg = nullptr;
    __half *p_Ah = nullptr, *p_Al = nullptr, *p_Bth = nullptr;
    cudaGetSymbolAddress((void**)&p_h, g_h);
    cudaGetSymbolAddress((void**)&p_agg, g_agg);
    cudaGetSymbolAddress((void**)&p_Ah, g_Ah);
    cudaGetSymbolAddress((void**)&p_Al, g_Al);
    cudaGetSymbolAddress((void**)&p_Bth, g_Bth);

    cudaFuncSetAttribute(mma_gemm_kernel,
                         cudaFuncAttributeMaxDynamicSharedMemorySize, GEMM_SMEM);

    const int ethreads = 256;
    const int eblocks = (ET + ethreads - 1) / ethreads;

    // CSR build
    zero_cnt_kernel<<<1, N_NODES>>>();
    build_edges_kernel<<<eblocks, ethreads>>>(ei);
    scan_kernel<<<1, N_NODES>>>();
    scatter_kernel<<<eblocks, ethreads>>>();

    dim3 ggrid(F_DIM / 128, N_NODES / 128);   // (64, 8)
    dim3 tb32(32, 32);

    // ---- layer 1 ----
    convA_kernel<<<dim3((KP1 + 255) / 256, N_NODES), 256>>>(x, IN_DIM, KP1, p_Ah, p_Al);
    convBt_kernel<<<dim3(KP1 / 32, F_DIM / 32), tb32>>>(W1, IN_DIM, KP1, p_Bth);
    mma_gemm_kernel<<<ggrid, 128, GEMM_SMEM>>>(p_Ah, p_Al, p_Bth, p_h, KP1, KP1 / 32);
    scores_kernel<<<N_NODES, 512>>>(p_h, as1, ad1);
    attn_kernel<<<N_NODES, 512>>>();
    agg_kernel<<<N_NODES, 256>>>(p_h, b1, p_agg);

    // ---- layer 2 ----
    convA_kernel<<<dim3(F_DIM / 256, N_NODES), 256>>>(p_agg, F_DIM, F_DIM, p_Ah, p_Al);
    convBt_kernel<<<dim3(F_DIM / 32, F_DIM / 32), tb32>>>(W2, F_DIM, F_DIM, p_Bth);
    mma_gemm_kernel<<<ggrid, 128, GEMM_SMEM>>>(p_Ah, p_Al, p_Bth, p_h, F_DIM, F_DIM / 32);
    scores_kernel<<<N_NODES, 512>>>(p_h, as2, ad2);
    attn_kernel<<<N_NODES, 512>>>();
    agg_kernel<<<N_NODES, 256>>>(p_h, b2, p_agg);

    // ---- readout ----
    nodedot_kernel<<<N_NODES, 256>>>(p_agg, lw);
    pool_kernel<<<1, N_NODES>>>(bat, lb, out);
}